// round 9
// baseline (speedup 1.0000x reference)
#include <cuda_runtime.h>
#include <cuda_fp16.h>
#include <cstdint>

// ---------------- problem constants ----------------
#define NB      16
#define INC     64
#define OUTC    64
#define HW      128
#define OW      126
#define FC      512
#define GROUPS  4
#define OPG     9232
#define IPG     128
#define CNNP    36928
#define NWCOL   36864

// ---------------- scratch (device-code refs only) ----------------
__device__ float g_h1[NB * FC];
__device__ float g_h2[NB * FC];
// pre-split, pre-swizzled weights: [b][ky][part][kx][oc][ic(swizzled units)]
__device__ __half g_wm[NB][3][2][3][64][64];
__device__ float g_bias[NB * OUTC];

// smem layout (dynamic): all-ky weights resident + double-buffered x rows
#define WKY       49152                 // one ky weight image
#define SM_WALL   0                     // 3 * WKY = 147456
#define SM_XB0    147456                // 2 x-row buffers
#define XBUF      40960
#define XPART     20480
#define SM_TOTAL  229376                // 147456 + 2*40960

#define NTILE_PER_CTA 14
#define NCTA          144               // 144 * 14 = 2016 tiles

// ---------------- PTX helpers ----------------
__device__ __forceinline__ unsigned int smem_u32(const void* p) {
    unsigned int a;
    asm("{ .reg .u64 t; cvta.to.shared.u64 t, %1; cvt.u32.u64 %0, t; }"
        : "=r"(a) : "l"(p));
    return a;
}
__device__ __forceinline__ void cp_async16(unsigned int sdst, const void* gsrc) {
    asm volatile("cp.async.cg.shared.global [%0], [%1], 16;" :: "r"(sdst), "l"(gsrc));
}
__device__ __forceinline__ void cp_commit() { asm volatile("cp.async.commit_group;"); }
__device__ __forceinline__ void cp_wait0()  { asm volatile("cp.async.wait_group 0;"); }

__device__ __forceinline__ void ldsm_x4(uint32_t& r0, uint32_t& r1, uint32_t& r2,
                                        uint32_t& r3, uint32_t addr) {
    asm volatile("ldmatrix.sync.aligned.m8n8.x4.shared.b16 {%0,%1,%2,%3}, [%4];"
                 : "=r"(r0), "=r"(r1), "=r"(r2), "=r"(r3) : "r"(addr));
}
__device__ __forceinline__ void mma16816(float* c, const uint32_t* a,
                                         uint32_t b0, uint32_t b1) {
    asm volatile(
        "mma.sync.aligned.m16n8k16.row.col.f32.f16.f16.f32 "
        "{%0,%1,%2,%3}, {%4,%5,%6,%7}, {%8,%9}, {%0,%1,%2,%3};"
        : "+f"(c[0]), "+f"(c[1]), "+f"(c[2]), "+f"(c[3])
        : "r"(a[0]), "r"(a[1]), "r"(a[2]), "r"(a[3]), "r"(b0), "r"(b1));
}
__device__ __forceinline__ uint32_t pack_h2(__half a, __half b) {
    return (uint32_t)__half_as_ushort(a) | ((uint32_t)__half_as_ushort(b) << 16);
}

// ============================================================
// Kernel 1: GEMV + bias + relu, warp-per-output.
// ============================================================
__device__ __forceinline__ void gemv_body(
    const float* __restrict__ in, const float* __restrict__ W,
    const float* __restrict__ bias, float* __restrict__ out)
{
    const int lane = threadIdx.x & 31;
    const int warp = threadIdx.x >> 5;
    const int b = blockIdx.y;
    const int t = blockIdx.x * 8 + warp;

    const float4* in4 = reinterpret_cast<const float4*>(in + (size_t)b * FC);
    const float4* w4  = reinterpret_cast<const float4*>(W + (size_t)t * FC);

    float s = 0.f;
    #pragma unroll
    for (int i = 0; i < 4; i++) {
        float4 a = in4[lane + 32 * i];
        float4 w = w4[lane + 32 * i];
        s += a.x * w.x + a.y * w.y + a.z * w.z + a.w * w.w;
    }
    #pragma unroll
    for (int off = 16; off > 0; off >>= 1)
        s += __shfl_xor_sync(0xffffffffu, s, off);
    if (lane == 0)
        out[(size_t)b * FC + t] = fmaxf(s + bias[t], 0.f);
}
__global__ __launch_bounds__(256) void gemv1_kernel(
    const float* __restrict__ fc_in, const float* __restrict__ w1,
    const float* __restrict__ b1) { gemv_body(fc_in, w1, b1, g_h1); }
__global__ __launch_bounds__(256) void gemv2_kernel(
    const float* __restrict__ w2, const float* __restrict__ b2) { gemv_body(g_h1, w2, b2, g_h2); }

// ============================================================
// Kernel 2: wbgen -> hi/lo-split, unit-swizzled weight images + bias.
// ============================================================
__global__ __launch_bounds__(256) void wbgen_kernel(
    const float* __restrict__ w3, const float* __restrict__ b3)
{
    __shared__ __align__(16) float4 s_h2[NB][IPG / 4];
    int g = blockIdx.x;
    int j = blockIdx.y * 256 + threadIdx.x;

    for (int e = threadIdx.x; e < NB * IPG / 4; e += 256) {
        int bb = e >> 5, k = e & 31;
        s_h2[bb][k] = reinterpret_cast<const float4*>(g_h2 + bb * FC + g * IPG)[k];
    }
    __syncthreads();
    if (j >= OPG) return;

    float acc[NB];
    #pragma unroll
    for (int bb = 0; bb < NB; bb++) acc[bb] = 0.f;

    const float4* wr = reinterpret_cast<const float4*>(w3 + ((size_t)g * OPG + j) * IPG);
    #pragma unroll 4
    for (int k = 0; k < IPG / 4; k++) {
        float4 w = wr[k];
        #pragma unroll
        for (int bb = 0; bb < NB; bb++) {
            float4 h = s_h2[bb][k];
            acc[bb] += w.x * h.x + w.y * h.y + w.z * h.z + w.w * h.w;
        }
    }
    float bias = b3[g * OPG + j];
    int col = g * OPG + j;

    if (col < NWCOL) {
        int oc = col / 576;
        int r  = col - oc * 576;
        int ic = r / 9;
        int kt = r - ic * 9;
        int ky = kt / 3;
        int kx = kt - ky * 3;
        int ic_sw = (((ic >> 3) ^ (oc & 7)) << 3) | (ic & 7);
        #pragma unroll
        for (int bb = 0; bb < NB; bb++) {
            float w = fmaxf(acc[bb] + bias, 0.f);
            __half hi = __float2half_rn(w);
            __half lo = __float2half_rn(w - __half2float(hi));
            g_wm[bb][ky][0][kx][oc][ic_sw] = hi;
            g_wm[bb][ky][1][kx][oc][ic_sw] = lo;
        }
    } else {
        int oc = col - NWCOL;
        #pragma unroll
        for (int bb = 0; bb < NB; bb++)
            g_bias[bb * OUTC + oc] = fmaxf(acc[bb] + bias, 0.f);
    }
}

// ============================================================
// Kernel 3: persistent HMMA implicit-GEMM conv.
// 144 CTAs x 14 tiles; tile = b*126 + oy. All-ky weights resident,
// x rows double-buffered with register prefetch across the MMA block.
// ============================================================
__global__ __launch_bounds__(256, 1) void conv_mma(
    const float* __restrict__ x, float* __restrict__ out)
{
    extern __shared__ char smem[];
    const uint32_t sb = smem_u32(smem);
    const int tid = threadIdx.x;
    const int w   = tid >> 5;
    const int L   = tid & 31;
    const int gq  = L >> 3;
    const int gi  = L & 7;
    const int ocw = (w & 1) * 32;
    const int pxw = (w >> 1) * 32;
    const int ic0 = w * 8;

    const int tile0 = blockIdx.x * NTILE_PER_CTA;
    const int nst   = NTILE_PER_CTA * 3;

    float acc[2][4][4];
    #pragma unroll
    for (int mt = 0; mt < 2; mt++)
        #pragma unroll
        for (int nt = 0; nt < 4; nt++)
            #pragma unroll
            for (int i = 0; i < 4; i++) acc[mt][nt][i] = 0.f;

    float v[5][8];   // prefetched x row

    // ---- helpers ----
    auto stage_w = [&](int b) {   // all 3 ky images, flat cp.async
        const char* src = reinterpret_cast<const char*>(&g_wm[b][0][0][0][0][0]);
        #pragma unroll 4
        for (int e = tid; e < 147456 / 16; e += 256)
            cp_async16(sb + SM_WALL + (uint32_t)e * 16, src + e * 16);
        cp_commit();
    };
    auto issue_x = [&](int tile, int ky) {
        int b  = tile / 126;
        int oy = tile - b * 126;
        const float* xr = x + ((size_t)b * INC * HW + (size_t)(oy + ky)) * HW;
        #pragma unroll
        for (int k = 0; k < 5; k++) {
            int c = k * 32 + L;
            if (k == 4 && c >= 130) continue;   // rows >129 never read
            int cc = c < HW ? c : HW - 1;
            #pragma unroll
            for (int i = 0; i < 8; i++)
                v[k][i] = __ldg(xr + (size_t)(ic0 + i) * HW * HW + cc);
        }
    };
    auto store_x = [&](int buf) {
        uint32_t xbase = SM_XB0 + (uint32_t)buf * XBUF;
        #pragma unroll
        for (int k = 0; k < 5; k++) {
            int c = k * 32 + L;
            if (k == 4 && c >= 130) continue;
            uint32_t hi[4], lo[4];
            #pragma unroll
            for (int i = 0; i < 4; i++) {
                __half h0 = __float2half_rn(v[k][2 * i]);
                __half h1 = __float2half_rn(v[k][2 * i + 1]);
                __half l0 = __float2half_rn(v[k][2 * i]     - __half2float(h0));
                __half l1 = __float2half_rn(v[k][2 * i + 1] - __half2float(h1));
                hi[i] = pack_h2(h0, h1);
                lo[i] = pack_h2(l0, l1);
            }
            uint32_t p   = (uint32_t)(w ^ (c & 7));
            uint32_t off = xbase + (uint32_t)c * 128u + p * 16u;
            *reinterpret_cast<uint4*>(smem + off)         = make_uint4(hi[0], hi[1], hi[2], hi[3]);
            *reinterpret_cast<uint4*>(smem + off + XPART) = make_uint4(lo[0], lo[1], lo[2], lo[3]);
        }
    };

    // ---- prologue ----
    int tile = tile0;
    int b    = tile / 126;
    int ky   = 0;
    stage_w(b);
    issue_x(tile, 0);
    store_x(0);
    cp_wait0();
    __syncthreads();

    // ---- pipelined main loop over stages s = (tile, ky) ----
    for (int s = 0; s < nst; s++) {
        const int snext = s + 1;
        const bool have_next = snext < nst;
        const int tnext = tile0 + snext / 3;
        const int kyn   = snext - 3 * (snext / 3);
        const int bn    = tnext / 126;

        if (have_next) issue_x(tnext, kyn);   // LDGs hidden under MMAs

        // ---- MMA block for (tile, ky) on buffer s&1 ----
        {
            const uint32_t wb_ = sb + SM_WALL + (uint32_t)ky * WKY;
            const uint32_t xb_ = sb + SM_XB0 + (uint32_t)(s & 1) * XBUF;
            for (int kx = 0; kx < 3; kx++) {
                #pragma unroll
                for (int ks = 0; ks < 4; ks++) {
                    const int ub = ks * 2;
                    uint32_t a[2][2][4];
                    #pragma unroll
                    for (int mt = 0; mt < 2; mt++) {
                        #pragma unroll
                        for (int part = 0; part < 2; part++) {
                            int row = ocw + mt * 16 + (gq & 1) * 8 + gi;
                            int u   = ub + (gq >> 1);
                            uint32_t addr = wb_ +
                                (uint32_t)(((part * 3 + kx) * 64 + row) * 128 +
                                           ((u ^ (row & 7)) * 16));
                            ldsm_x4(a[mt][part][0], a[mt][part][1],
                                    a[mt][part][2], a[mt][part][3], addr);
                        }
                    }
                    uint32_t bb[2][2][4];
                    #pragma unroll
                    for (int part = 0; part < 2; part++) {
                        #pragma unroll
                        for (int np = 0; np < 2; np++) {
                            int c = pxw + np * 16 + kx + (gq >> 1) * 8 + gi;
                            int u = ub + (gq & 1);
                            uint32_t addr = xb_ + (uint32_t)part * XPART +
                                (uint32_t)(c * 128 + ((u ^ (c & 7)) * 16));
                            ldsm_x4(bb[part][np][0], bb[part][np][1],
                                    bb[part][np][2], bb[part][np][3], addr);
                        }
                    }
                    #pragma unroll
                    for (int mt = 0; mt < 2; mt++) {
                        #pragma unroll
                        for (int nt = 0; nt < 4; nt++) {
                            int np = nt >> 1, q2 = (nt & 1) * 2;
                            mma16816(acc[mt][nt], a[mt][0], bb[0][np][q2], bb[0][np][q2 + 1]);
                            mma16816(acc[mt][nt], a[mt][0], bb[1][np][q2], bb[1][np][q2 + 1]);
                            mma16816(acc[mt][nt], a[mt][1], bb[0][np][q2], bb[0][np][q2 + 1]);
                        }
                    }
                }
            }
        }

        // ---- epilogue at tile end ----
        if (ky == 2) {
            const int oy = tile - b * 126;
            const float* bias = g_bias + b * OUTC;
            const int r4 = L >> 2;
            const int q  = (L & 3) * 2;
            #pragma unroll
            for (int mt = 0; mt < 2; mt++) {
                int oc = ocw + mt * 16 + r4;
                float bi0 = __ldg(bias + oc);
                float bi1 = __ldg(bias + oc + 8);
                #pragma unroll
                for (int nt = 0; nt < 4; nt++) {
                    int px = pxw + nt * 8 + q;
                    if (px < OW) {
                        float* o = out + (((size_t)(b * OUTC + oc)) * OW + oy) * OW + px;
                        float2 v0 = make_float2(acc[mt][nt][0] + bi0, acc[mt][nt][1] + bi0);
                        float2 v1 = make_float2(acc[mt][nt][2] + bi1, acc[mt][nt][3] + bi1);
                        *reinterpret_cast<float2*>(o) = v0;
                        *reinterpret_cast<float2*>(o + (size_t)8 * OW * OW) = v1;
                    }
                    #pragma unroll
                    for (int i = 0; i < 4; i++) acc[mt][nt][i] = 0.f;
                }
            }
        }

        if (have_next) {
            store_x(snext & 1);
            __syncthreads();                 // STS visible + old buffer free
            if (bn != b) {                   // new sample: restage weights
                stage_w(bn);
                cp_wait0();
                __syncthreads();
            }
        }
        tile = tnext; ky = kyn; b = bn;
    }
}

// ============================================================
extern "C" void kernel_launch(void* const* d_in, const int* in_sizes, int n_in,
                              void* d_out, int out_size)
{
    const float* x     = (const float*)d_in[0];
    const float* fc_in = (const float*)d_in[1];
    const float* w1    = (const float*)d_in[2];
    const float* b1    = (const float*)d_in[3];
    const float* w2    = (const float*)d_in[4];
    const float* b2    = (const float*)d_in[5];
    const float* w3    = (const float*)d_in[6];
    const float* b3    = (const float*)d_in[7];
    float* out = (float*)d_out;

    cudaFuncSetAttribute(conv_mma, cudaFuncAttributeMaxDynamicSharedMemorySize, SM_TOTAL);

    gemv1_kernel<<<dim3(FC / 8, NB), 256>>>(fc_in, w1, b1);
    gemv2_kernel<<<dim3(FC / 8, NB), 256>>>(w2, b2);
    wbgen_kernel<<<dim3(GROUPS, (OPG + 255) / 256), 256>>>(w3, b3);
    conv_mma<<<NCTA, 256, SM_TOTAL>>>(x, out);
}

// round 10
// speedup vs baseline: 1.1793x; 1.1793x over previous
#include <cuda_runtime.h>
#include <cuda_fp16.h>
#include <cstdint>

// ---------------- problem constants ----------------
#define NB      16
#define INC     64
#define OUTC    64
#define HW      128
#define OW      126
#define FC      512
#define GROUPS  4
#define OPG     9232
#define IPG     128
#define CNNP    36928
#define NWCOL   36864

// ---------------- scratch (device-code refs only) ----------------
__device__ float g_h1[NB * FC];
__device__ float g_h2[NB * FC];
// pre-split, pre-swizzled weights: [b][ky][kx][part][oc][ic(swizzled units)]
// kx-major so per-kx 16KB blocks are contiguous for pipelined cp.async groups.
__device__ __half g_wm[NB][3][3][2][64][64];
__device__ float g_bias[NB * OUTC];

// smem layout (dynamic)
#define SM_W      0          // 49152 B : [kx][part][oc][64 halves, swizzled units]
#define WKX       16384      // one kx block (2 parts x 64 oc x 128 B)
#define SM_X      49152      // 32768 B : [part][128 c-rows][64 halves, swizzled]
#define XPART     16384
#define SM_BIAS   81920      // 256 B
#define SM_TOTAL  82176

// ---------------- PTX helpers ----------------
__device__ __forceinline__ unsigned int smem_u32(const void* p) {
    unsigned int a;
    asm("{ .reg .u64 t; cvta.to.shared.u64 t, %1; cvt.u32.u64 %0, t; }"
        : "=r"(a) : "l"(p));
    return a;
}
__device__ __forceinline__ void cp_async16(unsigned int sdst, const void* gsrc) {
    asm volatile("cp.async.cg.shared.global [%0], [%1], 16;" :: "r"(sdst), "l"(gsrc));
}
__device__ __forceinline__ void cp_commit() { asm volatile("cp.async.commit_group;"); }
#define CP_WAIT_GROUP(n) asm volatile("cp.async.wait_group %0;" :: "n"(n))

__device__ __forceinline__ void ldsm_x4(uint32_t& r0, uint32_t& r1, uint32_t& r2,
                                        uint32_t& r3, uint32_t addr) {
    asm volatile("ldmatrix.sync.aligned.m8n8.x4.shared.b16 {%0,%1,%2,%3}, [%4];"
                 : "=r"(r0), "=r"(r1), "=r"(r2), "=r"(r3) : "r"(addr));
}
__device__ __forceinline__ void mma16816(float* c, const uint32_t* a,
                                         uint32_t b0, uint32_t b1) {
    asm volatile(
        "mma.sync.aligned.m16n8k16.row.col.f32.f16.f16.f32 "
        "{%0,%1,%2,%3}, {%4,%5,%6,%7}, {%8,%9}, {%0,%1,%2,%3};"
        : "+f"(c[0]), "+f"(c[1]), "+f"(c[2]), "+f"(c[3])
        : "r"(a[0]), "r"(a[1]), "r"(a[2]), "r"(a[3]), "r"(b0), "r"(b1));
}
__device__ __forceinline__ uint32_t pack_h2(__half a, __half b) {
    return (uint32_t)__half_as_ushort(a) | ((uint32_t)__half_as_ushort(b) << 16);
}

// ============================================================
// Kernel 1: GEMV + bias + relu, warp-per-output.
// ============================================================
__device__ __forceinline__ void gemv_body(
    const float* __restrict__ in, const float* __restrict__ W,
    const float* __restrict__ bias, float* __restrict__ out)
{
    const int lane = threadIdx.x & 31;
    const int warp = threadIdx.x >> 5;
    const int b = blockIdx.y;
    const int t = blockIdx.x * 8 + warp;

    const float4* in4 = reinterpret_cast<const float4*>(in + (size_t)b * FC);
    const float4* w4  = reinterpret_cast<const float4*>(W + (size_t)t * FC);

    float s = 0.f;
    #pragma unroll
    for (int i = 0; i < 4; i++) {
        float4 a = in4[lane + 32 * i];
        float4 w = w4[lane + 32 * i];
        s += a.x * w.x + a.y * w.y + a.z * w.z + a.w * w.w;
    }
    #pragma unroll
    for (int off = 16; off > 0; off >>= 1)
        s += __shfl_xor_sync(0xffffffffu, s, off);
    if (lane == 0)
        out[(size_t)b * FC + t] = fmaxf(s + bias[t], 0.f);
}
__global__ __launch_bounds__(256) void gemv1_kernel(
    const float* __restrict__ fc_in, const float* __restrict__ w1,
    const float* __restrict__ b1) { gemv_body(fc_in, w1, b1, g_h1); }
__global__ __launch_bounds__(256) void gemv2_kernel(
    const float* __restrict__ w2, const float* __restrict__ b2) { gemv_body(g_h1, w2, b2, g_h2); }

// ============================================================
// Kernel 2: wbgen -> hi/lo-split, unit-swizzled weight images + bias.
// ============================================================
__global__ __launch_bounds__(256) void wbgen_kernel(
    const float* __restrict__ w3, const float* __restrict__ b3)
{
    __shared__ __align__(16) float4 s_h2[NB][IPG / 4];
    int g = blockIdx.x;
    int j = blockIdx.y * 256 + threadIdx.x;

    for (int e = threadIdx.x; e < NB * IPG / 4; e += 256) {
        int bb = e >> 5, k = e & 31;
        s_h2[bb][k] = reinterpret_cast<const float4*>(g_h2 + bb * FC + g * IPG)[k];
    }
    __syncthreads();
    if (j >= OPG) return;

    float acc[NB];
    #pragma unroll
    for (int bb = 0; bb < NB; bb++) acc[bb] = 0.f;

    const float4* wr = reinterpret_cast<const float4*>(w3 + ((size_t)g * OPG + j) * IPG);
    #pragma unroll 4
    for (int k = 0; k < IPG / 4; k++) {
        float4 w = wr[k];
        #pragma unroll
        for (int bb = 0; bb < NB; bb++) {
            float4 h = s_h2[bb][k];
            acc[bb] += w.x * h.x + w.y * h.y + w.z * h.z + w.w * h.w;
        }
    }
    float bias = b3[g * OPG + j];
    int col = g * OPG + j;

    if (col < NWCOL) {
        // col = oc*576 + ic*9 + ky*3 + kx
        int oc = col / 576;
        int r  = col - oc * 576;
        int ic = r / 9;
        int kt = r - ic * 9;
        int ky = kt / 3;
        int kx = kt - ky * 3;
        int ic_sw = (((ic >> 3) ^ (oc & 7)) << 3) | (ic & 7);
        #pragma unroll
        for (int bb = 0; bb < NB; bb++) {
            float w = fmaxf(acc[bb] + bias, 0.f);
            __half hi = __float2half_rn(w);
            __half lo = __float2half_rn(w - __half2float(hi));
            g_wm[bb][ky][kx][0][oc][ic_sw] = hi;
            g_wm[bb][ky][kx][1][oc][ic_sw] = lo;
        }
    } else {
        int oc = col - NWCOL;
        #pragma unroll
        for (int bb = 0; bb < NB; bb++)
            g_bias[bb * OUTC + oc] = fmaxf(acc[bb] + bias, 0.f);
    }
}

// ============================================================
// Kernel 3: HMMA implicit-GEMM conv, kx-pipelined weight staging.
// CTA = (output row oy, sample b). D[oc 64][px 128] over K=576.
// Per ky: 3 cp.async groups (one per kx, 16KB); MMA(kx) starts as soon
// as its group lands, later groups drain under earlier MMAs.
// ============================================================
__global__ __launch_bounds__(256, 2) void conv_mma(
    const float* __restrict__ x, float* __restrict__ out)
{
    extern __shared__ char smem[];
    const uint32_t sb = smem_u32(smem);
    const int tid = threadIdx.x;
    const int w   = tid >> 5;
    const int L   = tid & 31;
    const int gq  = L >> 3;
    const int gi  = L & 7;
    const int ocw = (w & 1) * 32;
    const int pxw = (w >> 1) * 32;
    const int ic0 = w * 8;
    const int oy  = blockIdx.x;      // 0..125
    const int b   = blockIdx.y;      // 0..15

    float* s_bias = reinterpret_cast<float*>(smem + SM_BIAS);
    if (tid < OUTC) s_bias[tid] = g_bias[b * OUTC + tid];

    float acc[2][4][4];
    #pragma unroll
    for (int mt = 0; mt < 2; mt++)
        #pragma unroll
        for (int nt = 0; nt < 4; nt++)
            #pragma unroll
            for (int i = 0; i < 4; i++) acc[mt][nt][i] = 0.f;

    // MMA block for one kx (reads W block kx and x buffer)
    auto mma_kx = [&](int kx) {
        #pragma unroll
        for (int ks = 0; ks < 4; ks++) {
            const int ub = ks * 2;
            uint32_t a[2][2][4];
            #pragma unroll
            for (int mt = 0; mt < 2; mt++) {
                #pragma unroll
                for (int part = 0; part < 2; part++) {
                    int row = ocw + mt * 16 + (gq & 1) * 8 + gi;
                    int u   = ub + (gq >> 1);
                    uint32_t addr = sb + SM_W +
                        (uint32_t)(((kx * 2 + part) * 64 + row) * 128 +
                                   ((u ^ (row & 7)) * 16));
                    ldsm_x4(a[mt][part][0], a[mt][part][1],
                            a[mt][part][2], a[mt][part][3], addr);
                }
            }
            uint32_t bb[2][2][4];
            #pragma unroll
            for (int part = 0; part < 2; part++) {
                #pragma unroll
                for (int np = 0; np < 2; np++) {
                    int c = pxw + np * 16 + kx + (gq >> 1) * 8 + gi;
                    if (c > 127) c = 127;   // rows >127 feed only discarded px
                    uint32_t addr = sb + SM_X + (uint32_t)part * XPART +
                        (uint32_t)(c * 128 + (((ub + (gq & 1)) ^ (c & 7)) * 16));
                    ldsm_x4(bb[part][np][0], bb[part][np][1],
                            bb[part][np][2], bb[part][np][3], addr);
                }
            }
            #pragma unroll
            for (int mt = 0; mt < 2; mt++) {
                #pragma unroll
                for (int nt = 0; nt < 4; nt++) {
                    int np = nt >> 1, q2 = (nt & 1) * 2;
                    mma16816(acc[mt][nt], a[mt][0], bb[0][np][q2], bb[0][np][q2 + 1]);
                    mma16816(acc[mt][nt], a[mt][0], bb[1][np][q2], bb[1][np][q2 + 1]);
                    mma16816(acc[mt][nt], a[mt][1], bb[0][np][q2], bb[0][np][q2 + 1]);
                }
            }
        }
    };

    for (int ky = 0; ky < 3; ky++) {
        __syncthreads();   // prior MMAs done before overwriting tiles

        // ---- stage weights: 3 commit groups, one per kx (16KB each) ----
        {
            const char* src = reinterpret_cast<const char*>(&g_wm[b][ky][0][0][0][0]);
            #pragma unroll
            for (int g = 0; g < 3; g++) {
                #pragma unroll
                for (int i = 0; i < 4; i++) {
                    uint32_t e = (uint32_t)(tid + i * 256) * 16 + (uint32_t)g * WKX;
                    cp_async16(sb + SM_W + e, src + e);
                }
                cp_commit();
            }
        }

        // ---- stage x row (transpose + hi/lo split): s_x[part][c][ic] ----
        {
            const float* xr = x + ((size_t)b * INC * HW + (size_t)(oy + ky)) * HW;
            #pragma unroll
            for (int k = 0; k < 4; k++) {
                int c = k * 32 + L;            // 0..127
                float v[8];
                #pragma unroll
                for (int i = 0; i < 8; i++)
                    v[i] = __ldg(xr + (size_t)(ic0 + i) * HW * HW + c);
                uint32_t hi[4], lo[4];
                #pragma unroll
                for (int i = 0; i < 4; i++) {
                    __half h0 = __float2half_rn(v[2 * i]);
                    __half h1 = __float2half_rn(v[2 * i + 1]);
                    __half l0 = __float2half_rn(v[2 * i]     - __half2float(h0));
                    __half l1 = __float2half_rn(v[2 * i + 1] - __half2float(h1));
                    hi[i] = pack_h2(h0, h1);
                    lo[i] = pack_h2(l0, l1);
                }
                uint32_t p   = (uint32_t)(w ^ (c & 7));
                uint32_t off = SM_X + (uint32_t)c * 128u + p * 16u;
                *reinterpret_cast<uint4*>(smem + off)         = make_uint4(hi[0], hi[1], hi[2], hi[3]);
                *reinterpret_cast<uint4*>(smem + off + XPART) = make_uint4(lo[0], lo[1], lo[2], lo[3]);
            }
        }

        // ---- kx-pipelined MMA: wait only for the kx block needed ----
        CP_WAIT_GROUP(2);
        __syncthreads();       // x STS + W(kx0) visible CTA-wide
        mma_kx(0);
        CP_WAIT_GROUP(1);
        __syncthreads();
        mma_kx(1);
        CP_WAIT_GROUP(0);
        __syncthreads();
        mma_kx(2);
    }

    // ---- epilogue: + bias, store float2 (px pairs even-aligned) ----
    const int r4 = L >> 2;
    const int q  = (L & 3) * 2;
    #pragma unroll
    for (int mt = 0; mt < 2; mt++) {
        int oc = ocw + mt * 16 + r4;
        float bi0 = s_bias[oc];
        float bi1 = s_bias[oc + 8];
        #pragma unroll
        for (int nt = 0; nt < 4; nt++) {
            int px = pxw + nt * 8 + q;
            if (px < OW) {
                float* o = out + (((size_t)(b * OUTC + oc)) * OW + oy) * OW + px;
                float2 v0 = make_float2(acc[mt][nt][0] + bi0, acc[mt][nt][1] + bi0);
                float2 v1 = make_float2(acc[mt][nt][2] + bi1, acc[mt][nt][3] + bi1);
                *reinterpret_cast<float2*>(o) = v0;
                *reinterpret_cast<float2*>(o + (size_t)8 * OW * OW) = v1;
            }
        }
    }
}

// ============================================================
extern "C" void kernel_launch(void* const* d_in, const int* in_sizes, int n_in,
                              void* d_out, int out_size)
{
    const float* x     = (const float*)d_in[0];
    const float* fc_in = (const float*)d_in[1];
    const float* w1    = (const float*)d_in[2];
    const float* b1    = (const float*)d_in[3];
    const float* w2    = (const float*)d_in[4];
    const float* b2    = (const float*)d_in[5];
    const float* w3    = (const float*)d_in[6];
    const float* b3    = (const float*)d_in[7];
    float* out = (float*)d_out;

    cudaFuncSetAttribute(conv_mma, cudaFuncAttributeMaxDynamicSharedMemorySize, SM_TOTAL);

    gemv1_kernel<<<dim3(FC / 8, NB), 256>>>(fc_in, w1, b1);
    gemv2_kernel<<<dim3(FC / 8, NB), 256>>>(w2, b2);
    wbgen_kernel<<<dim3(GROUPS, (OPG + 255) / 256), 256>>>(w3, b3);
    conv_mma<<<dim3(OW, NB), 256, SM_TOTAL>>>(x, out);
}

// round 11
// speedup vs baseline: 1.2222x; 1.0364x over previous
#include <cuda_runtime.h>
#include <cuda_fp16.h>
#include <cstdint>

// ---------------- problem constants ----------------
#define NB      16
#define INC     64
#define OUTC    64
#define HW      128
#define OW      126
#define FC      512
#define GROUPS  4
#define OPG     9232
#define IPG     128
#define CNNP    36928
#define NWCOL   36864

// ---------------- scratch (device-code refs only) ----------------
__device__ float g_h1[NB * FC];
__device__ float g_h2[NB * FC];
// pre-split, pre-swizzled weights: [b][ky][kx][part][oc][ic(swizzled units)]
__device__ __half g_wm[NB][3][3][2][64][64];
__device__ float g_bias[NB * OUTC];

// smem layout (dynamic)
#define WIMG      49152      // one ky weight image
#define SM_W      0          // 2 x WIMG (double buffer)
#define SM_X      98304      // 2 x 32768 (double buffer)
#define XBUF      32768
#define XPART     16384
#define SM_BIAS   163840     // 256 B
#define SM_TOTAL  164096

#define TILES_PER_CTA 7
#define CTA_PER_B     18     // 18 * 7 = 126 rows
#define NSTAGE        (TILES_PER_CTA * 3)   // 21

// named barriers: FULL = 1+buf, EMPTY = 3+buf, 512 threads each
#define BAR_SYNC(id)   asm volatile("bar.sync %0, 512;"   :: "r"(id) : "memory")
#define BAR_ARRIVE(id) asm volatile("bar.arrive %0, 512;" :: "r"(id) : "memory")

// ---------------- PTX helpers ----------------
__device__ __forceinline__ unsigned int smem_u32(const void* p) {
    unsigned int a;
    asm("{ .reg .u64 t; cvta.to.shared.u64 t, %1; cvt.u32.u64 %0, t; }"
        : "=r"(a) : "l"(p));
    return a;
}
__device__ __forceinline__ void cp_async16(unsigned int sdst, const void* gsrc) {
    asm volatile("cp.async.cg.shared.global [%0], [%1], 16;" :: "r"(sdst), "l"(gsrc));
}
__device__ __forceinline__ void cp_commit() { asm volatile("cp.async.commit_group;"); }
__device__ __forceinline__ void cp_wait0()  { asm volatile("cp.async.wait_group 0;"); }

__device__ __forceinline__ void ldsm_x4(uint32_t& r0, uint32_t& r1, uint32_t& r2,
                                        uint32_t& r3, uint32_t addr) {
    asm volatile("ldmatrix.sync.aligned.m8n8.x4.shared.b16 {%0,%1,%2,%3}, [%4];"
                 : "=r"(r0), "=r"(r1), "=r"(r2), "=r"(r3) : "r"(addr));
}
__device__ __forceinline__ void mma16816(float* c, const uint32_t* a,
                                         uint32_t b0, uint32_t b1) {
    asm volatile(
        "mma.sync.aligned.m16n8k16.row.col.f32.f16.f16.f32 "
        "{%0,%1,%2,%3}, {%4,%5,%6,%7}, {%8,%9}, {%0,%1,%2,%3};"
        : "+f"(c[0]), "+f"(c[1]), "+f"(c[2]), "+f"(c[3])
        : "r"(a[0]), "r"(a[1]), "r"(a[2]), "r"(a[3]), "r"(b0), "r"(b1));
}
__device__ __forceinline__ uint32_t pack_h2(__half a, __half b) {
    return (uint32_t)__half_as_ushort(a) | ((uint32_t)__half_as_ushort(b) << 16);
}

// ============================================================
// Kernel 1: GEMV + bias + relu, warp-per-output.
// ============================================================
__device__ __forceinline__ void gemv_body(
    const float* __restrict__ in, const float* __restrict__ W,
    const float* __restrict__ bias, float* __restrict__ out)
{
    const int lane = threadIdx.x & 31;
    const int warp = threadIdx.x >> 5;
    const int b = blockIdx.y;
    const int t = blockIdx.x * 8 + warp;

    const float4* in4 = reinterpret_cast<const float4*>(in + (size_t)b * FC);
    const float4* w4  = reinterpret_cast<const float4*>(W + (size_t)t * FC);

    float s = 0.f;
    #pragma unroll
    for (int i = 0; i < 4; i++) {
        float4 a = in4[lane + 32 * i];
        float4 w = w4[lane + 32 * i];
        s += a.x * w.x + a.y * w.y + a.z * w.z + a.w * w.w;
    }
    #pragma unroll
    for (int off = 16; off > 0; off >>= 1)
        s += __shfl_xor_sync(0xffffffffu, s, off);
    if (lane == 0)
        out[(size_t)b * FC + t] = fmaxf(s + bias[t], 0.f);
}
__global__ __launch_bounds__(256) void gemv1_kernel(
    const float* __restrict__ fc_in, const float* __restrict__ w1,
    const float* __restrict__ b1) { gemv_body(fc_in, w1, b1, g_h1); }
__global__ __launch_bounds__(256) void gemv2_kernel(
    const float* __restrict__ w2, const float* __restrict__ b2) { gemv_body(g_h1, w2, b2, g_h2); }

// ============================================================
// Kernel 2: wbgen -> hi/lo-split, unit-swizzled weight images + bias.
// ============================================================
__global__ __launch_bounds__(256) void wbgen_kernel(
    const float* __restrict__ w3, const float* __restrict__ b3)
{
    __shared__ __align__(16) float4 s_h2[NB][IPG / 4];
    int g = blockIdx.x;
    int j = blockIdx.y * 256 + threadIdx.x;

    for (int e = threadIdx.x; e < NB * IPG / 4; e += 256) {
        int bb = e >> 5, k = e & 31;
        s_h2[bb][k] = reinterpret_cast<const float4*>(g_h2 + bb * FC + g * IPG)[k];
    }
    __syncthreads();
    if (j >= OPG) return;

    float acc[NB];
    #pragma unroll
    for (int bb = 0; bb < NB; bb++) acc[bb] = 0.f;

    const float4* wr = reinterpret_cast<const float4*>(w3 + ((size_t)g * OPG + j) * IPG);
    #pragma unroll 4
    for (int k = 0; k < IPG / 4; k++) {
        float4 w = wr[k];
        #pragma unroll
        for (int bb = 0; bb < NB; bb++) {
            float4 h = s_h2[bb][k];
            acc[bb] += w.x * h.x + w.y * h.y + w.z * h.z + w.w * h.w;
        }
    }
    float bias = b3[g * OPG + j];
    int col = g * OPG + j;

    if (col < NWCOL) {
        // col = oc*576 + ic*9 + ky*3 + kx
        int oc = col / 576;
        int r  = col - oc * 576;
        int ic = r / 9;
        int kt = r - ic * 9;
        int ky = kt / 3;
        int kx = kt - ky * 3;
        int ic_sw = (((ic >> 3) ^ (oc & 7)) << 3) | (ic & 7);
        #pragma unroll
        for (int bb = 0; bb < NB; bb++) {
            float w = fmaxf(acc[bb] + bias, 0.f);
            __half hi = __float2half_rn(w);
            __half lo = __float2half_rn(w - __half2float(hi));
            g_wm[bb][ky][kx][0][oc][ic_sw] = hi;
            g_wm[bb][ky][kx][1][oc][ic_sw] = lo;
        }
    } else {
        int oc = col - NWCOL;
        #pragma unroll
        for (int bb = 0; bb < NB; bb++)
            g_bias[bb * OUTC + oc] = fmaxf(acc[bb] + bias, 0.f);
    }
}

// ============================================================
// Kernel 3: warp-specialized HMMA implicit-GEMM conv.
// 512 threads: warps 0-7 consumers (MMA), warps 8-15 producers (staging).
// CTA owns 7 consecutive output rows of one sample; 21 stages = (tile, ky),
// double-buffered W image + x row, named-barrier full/empty pipeline.
// ============================================================
__global__ __launch_bounds__(512, 1) void conv_mma(
    const float* __restrict__ x, float* __restrict__ out)
{
    extern __shared__ char smem[];
    const uint32_t sb = smem_u32(smem);
    const int tid  = threadIdx.x;
    const int warp = tid >> 5;
    const int L    = tid & 31;

    const int b   = blockIdx.x / CTA_PER_B;
    const int oy0 = (blockIdx.x - b * CTA_PER_B) * TILES_PER_CTA;

    float* s_bias = reinterpret_cast<float*>(smem + SM_BIAS);
    if (tid < OUTC) s_bias[tid] = g_bias[b * OUTC + tid];

    if (warp < 8) {
        // ======================= CONSUMERS =======================
        const int gq  = L >> 3;
        const int gi  = L & 7;
        const int ocw = (warp & 1) * 32;
        const int pxw = (warp >> 1) * 32;

        float acc[2][4][4];
        #pragma unroll
        for (int mt = 0; mt < 2; mt++)
            #pragma unroll
            for (int nt = 0; nt < 4; nt++)
                #pragma unroll
                for (int i = 0; i < 4; i++) acc[mt][nt][i] = 0.f;

        for (int s = 0; s < NSTAGE; s++) {
            const int buf = s & 1;
            BAR_SYNC(1 + buf);                       // wait FULL

            const uint32_t wb_ = sb + SM_W + (uint32_t)buf * WIMG;
            const uint32_t xb_ = sb + SM_X + (uint32_t)buf * XBUF;

            for (int kx = 0; kx < 3; kx++) {
                #pragma unroll
                for (int ks = 0; ks < 4; ks++) {
                    const int ub = ks * 2;
                    uint32_t a[2][2][4];
                    #pragma unroll
                    for (int mt = 0; mt < 2; mt++) {
                        #pragma unroll
                        for (int part = 0; part < 2; part++) {
                            int row = ocw + mt * 16 + (gq & 1) * 8 + gi;
                            int u   = ub + (gq >> 1);
                            uint32_t addr = wb_ +
                                (uint32_t)(((kx * 2 + part) * 64 + row) * 128 +
                                           ((u ^ (row & 7)) * 16));
                            ldsm_x4(a[mt][part][0], a[mt][part][1],
                                    a[mt][part][2], a[mt][part][3], addr);
                        }
                    }
                    uint32_t bb[2][2][4];
                    #pragma unroll
                    for (int part = 0; part < 2; part++) {
                        #pragma unroll
                        for (int np = 0; np < 2; np++) {
                            int c = pxw + np * 16 + kx + (gq >> 1) * 8 + gi;
                            if (c > 127) c = 127;    // feeds only discarded px
                            uint32_t addr = xb_ + (uint32_t)part * XPART +
                                (uint32_t)(c * 128 + (((ub + (gq & 1)) ^ (c & 7)) * 16));
                            ldsm_x4(bb[part][np][0], bb[part][np][1],
                                    bb[part][np][2], bb[part][np][3], addr);
                        }
                    }
                    #pragma unroll
                    for (int mt = 0; mt < 2; mt++) {
                        #pragma unroll
                        for (int nt = 0; nt < 4; nt++) {
                            int np = nt >> 1, q2 = (nt & 1) * 2;
                            mma16816(acc[mt][nt], a[mt][0], bb[0][np][q2], bb[0][np][q2 + 1]);
                            mma16816(acc[mt][nt], a[mt][0], bb[1][np][q2], bb[1][np][q2 + 1]);
                            mma16816(acc[mt][nt], a[mt][1], bb[0][np][q2], bb[0][np][q2 + 1]);
                        }
                    }
                }
            }

            BAR_ARRIVE(3 + buf);                     // signal EMPTY

            // ---- epilogue at tile end ----
            if (s % 3 == 2) {
                const int oy = oy0 + s / 3;
                const int r4 = L >> 2;
                const int q  = (L & 3) * 2;
                #pragma unroll
                for (int mt = 0; mt < 2; mt++) {
                    int oc = ocw + mt * 16 + r4;
                    float bi0 = s_bias[oc];
                    float bi1 = s_bias[oc + 8];
                    #pragma unroll
                    for (int nt = 0; nt < 4; nt++) {
                        int px = pxw + nt * 8 + q;
                        if (px < OW) {
                            float* o = out + (((size_t)(b * OUTC + oc)) * OW + oy) * OW + px;
                            float2 v0 = make_float2(acc[mt][nt][0] + bi0, acc[mt][nt][1] + bi0);
                            float2 v1 = make_float2(acc[mt][nt][2] + bi1, acc[mt][nt][3] + bi1);
                            *reinterpret_cast<float2*>(o) = v0;
                            *reinterpret_cast<float2*>(o + (size_t)8 * OW * OW) = v1;
                        }
                        #pragma unroll
                        for (int i = 0; i < 4; i++) acc[mt][nt][i] = 0.f;
                    }
                }
            }
        }
    } else {
        // ======================= PRODUCERS =======================
        const int pw   = warp - 8;       // 0..7
        const int ptid = tid - 256;      // 0..255
        const int ic0  = pw * 8;

        for (int s = 0; s < NSTAGE; s++) {
            const int buf  = s & 1;
            const int tile = s / 3;
            const int ky   = s - 3 * tile;

            if (s >= 2) BAR_SYNC(3 + buf);           // wait EMPTY

            // ---- W image for (b, ky): flat cp.async (48 KB) ----
            {
                const char* src = reinterpret_cast<const char*>(&g_wm[b][ky][0][0][0][0]);
                const uint32_t dst = sb + SM_W + (uint32_t)buf * WIMG;
                #pragma unroll
                for (int i = 0; i < 12; i++) {
                    uint32_t e = ((uint32_t)ptid + (uint32_t)i * 256u) * 16u;
                    cp_async16(dst + e, src + e);
                }
                cp_commit();
            }

            // ---- x row y = oy0 + tile + ky: LDG -> hi/lo cvt -> STS ----
            {
                const int y = oy0 + tile + ky;       // <= 127
                const float* xr = x + ((size_t)b * INC * HW + (size_t)y) * HW;
                const uint32_t xbase = SM_X + (uint32_t)buf * XBUF;
                #pragma unroll
                for (int k = 0; k < 4; k++) {
                    int c = k * 32 + L;              // 0..127
                    float v[8];
                    #pragma unroll
                    for (int i = 0; i < 8; i++)
                        v[i] = __ldg(xr + (size_t)(ic0 + i) * HW * HW + c);
                    uint32_t hi[4], lo[4];
                    #pragma unroll
                    for (int i = 0; i < 4; i++) {
                        __half h0 = __float2half_rn(v[2 * i]);
                        __half h1 = __float2half_rn(v[2 * i + 1]);
                        __half l0 = __float2half_rn(v[2 * i]     - __half2float(h0));
                        __half l1 = __float2half_rn(v[2 * i + 1] - __half2float(h1));
                        hi[i] = pack_h2(h0, h1);
                        lo[i] = pack_h2(l0, l1);
                    }
                    uint32_t p   = (uint32_t)(pw ^ (c & 7));
                    uint32_t off = xbase + (uint32_t)c * 128u + p * 16u;
                    *reinterpret_cast<uint4*>(smem + off)         = make_uint4(hi[0], hi[1], hi[2], hi[3]);
                    *reinterpret_cast<uint4*>(smem + off + XPART) = make_uint4(lo[0], lo[1], lo[2], lo[3]);
                }
            }

            cp_wait0();                              // W copies landed
            BAR_ARRIVE(1 + buf);                     // signal FULL
        }
    }
}

// ============================================================
extern "C" void kernel_launch(void* const* d_in, const int* in_sizes, int n_in,
                              void* d_out, int out_size)
{
    const float* x     = (const float*)d_in[0];
    const float* fc_in = (const float*)d_in[1];
    const float* w1    = (const float*)d_in[2];
    const float* b1    = (const float*)d_in[3];
    const float* w2    = (const float*)d_in[4];
    const float* b2    = (const float*)d_in[5];
    const float* w3    = (const float*)d_in[6];
    const float* b3    = (const float*)d_in[7];
    float* out = (float*)d_out;

    cudaFuncSetAttribute(conv_mma, cudaFuncAttributeMaxDynamicSharedMemorySize, SM_TOTAL);

    gemv1_kernel<<<dim3(FC / 8, NB), 256>>>(fc_in, w1, b1);
    gemv2_kernel<<<dim3(FC / 8, NB), 256>>>(w2, b2);
    wbgen_kernel<<<dim3(GROUPS, (OPG + 255) / 256), 256>>>(w3, b3);
    conv_mma<<<NB * CTA_PER_B, 512, SM_TOTAL>>>(x, out);
}